// round 11
// baseline (speedup 1.0000x reference)
#include <cuda_runtime.h>
#include <cstdint>

#define C   128
#define LDK 136   // smem row stride (floats): 8-bank stride => conflict-free half-warp phases
#define TME 32    // edge tile rows per group
#define NG  4     // independent 2-warp groups per CTA

extern __shared__ char dynsmem[];

// ---------------- scratch (device globals; allocation-free rule) ----------------
static __device__ __align__(16) float g_xf[20480 * C];
static __device__ __align__(16) float g_agg[20480 * C];
static __device__ __align__(16) float g_W1t[C * C];
static __device__ __align__(16) float g_W2t[C * C];
static __device__ __align__(16) float g_Wit[C * C];
static __device__ __align__(16) float g_Wot[C * C];
static __device__ __align__(16) float g_Wdt[C * C];

__device__ __forceinline__ float ssp_f(float x) {
    float t = __expf(-fabsf(x));
    return fmaxf(x, 0.0f) + __logf(1.0f + t) - 0.693147180559945f;
}

__device__ __forceinline__ float to_tf32(float x) {
    uint32_t u;
    asm("cvt.rna.tf32.f32 %0, %1;" : "=r"(u) : "f"(x));
    return __uint_as_float(u);
}

__device__ __forceinline__ void mma_tf32(float* d, const uint32_t* a, const uint32_t* b) {
    asm volatile(
        "mma.sync.aligned.m16n8k8.row.col.f32.tf32.tf32.f32 "
        "{%0,%1,%2,%3}, {%4,%5,%6,%7}, {%8,%9}, {%0,%1,%2,%3};"
        : "+f"(d[0]), "+f"(d[1]), "+f"(d[2]), "+f"(d[3])
        : "r"(a[0]), "r"(a[1]), "r"(a[2]), "r"(a[3]), "r"(b[0]), "r"(b[1]));
}

// Octet k-interleave: logical k j8 -> phys ((j8&3)<<1)|(j8>>2); pair {2c,2c+1} is one LDS.64.

__device__ __forceinline__ void load_w_tile(float* dst, const float* __restrict__ src,
                                            int tid, int nthr) {
    for (int idx = tid; idx < 128 * 32; idx += nthr) {
        int row = idx >> 5, c4 = idx & 31;
        float4 v = ((const float4*)src)[idx];
        float* d = dst + row * LDK + (c4 >> 1) * 8 + (c4 & 1);
        d[0] = to_tf32(v.x); d[2] = to_tf32(v.y); d[4] = to_tf32(v.z); d[6] = to_tf32(v.w);
    }
}

__device__ __forceinline__ void load_a_tile(float* dst, const float* __restrict__ src,
                                            int base, int nrow_total, int rows,
                                            int tid, int nthr) {
    for (int idx = tid; idx < rows * 32; idx += nthr) {
        int row = idx >> 5, c4 = idx & 31;
        float4 v = make_float4(0.f, 0.f, 0.f, 0.f);
        int gr = base + row;
        if (gr < nrow_total) v = ((const float4*)src)[gr * 32 + c4];
        float* d = dst + row * LDK + (c4 >> 1) * 8 + (c4 & 1);
        d[0] = to_tf32(v.x); d[2] = to_tf32(v.y); d[4] = to_tf32(v.z); d[6] = to_tf32(v.w);
    }
}

// warp's 32x64 output tile over k=128 (A-frags amortize B over n64)
__device__ __forceinline__ void gemm32x64(const float* pa, const float* pb, float acc[2][8][4]) {
#pragma unroll
    for (int mt = 0; mt < 2; ++mt)
#pragma unroll
        for (int nt = 0; nt < 8; ++nt)
#pragma unroll
            for (int q = 0; q < 4; ++q) acc[mt][nt][q] = 0.f;
#pragma unroll
    for (int kk = 0; kk < 16; ++kk) {
        const int kb = kk * 8;
        uint32_t af[2][4], bf[8][2];
#pragma unroll
        for (int mt = 0; mt < 2; ++mt) {
            float2 xv = *(const float2*)(pa + mt * 16 * LDK + kb);
            float2 yv = *(const float2*)(pa + (mt * 16 + 8) * LDK + kb);
            af[mt][0] = __float_as_uint(xv.x); af[mt][2] = __float_as_uint(xv.y);
            af[mt][1] = __float_as_uint(yv.x); af[mt][3] = __float_as_uint(yv.y);
        }
#pragma unroll
        for (int nt = 0; nt < 8; ++nt) {
            float2 zv = *(const float2*)(pb + nt * 8 * LDK + kb);
            bf[nt][0] = __float_as_uint(zv.x); bf[nt][1] = __float_as_uint(zv.y);
        }
#pragma unroll
        for (int mt = 0; mt < 2; ++mt)
#pragma unroll
            for (int nt = 0; nt < 8; ++nt)
                mma_tf32(acc[mt][nt], af[mt], bf[nt]);
    }
}

// 32x32 warp tile (atom kernels keep the old shape)
__device__ __forceinline__ void gemm32x32(const float* pa, const float* pb, float acc[2][4][4]) {
#pragma unroll
    for (int mt = 0; mt < 2; ++mt)
#pragma unroll
        for (int nt = 0; nt < 4; ++nt)
#pragma unroll
            for (int q = 0; q < 4; ++q) acc[mt][nt][q] = 0.f;
#pragma unroll
    for (int kk = 0; kk < 16; ++kk) {
        const int kb = kk * 8;
        uint32_t af[2][4], bf[4][2];
#pragma unroll
        for (int mt = 0; mt < 2; ++mt) {
            float2 xv = *(const float2*)(pa + mt * 16 * LDK + kb);
            float2 yv = *(const float2*)(pa + (mt * 16 + 8) * LDK + kb);
            af[mt][0] = __float_as_uint(xv.x); af[mt][2] = __float_as_uint(xv.y);
            af[mt][1] = __float_as_uint(yv.x); af[mt][3] = __float_as_uint(yv.y);
        }
#pragma unroll
        for (int nt = 0; nt < 4; ++nt) {
            float2 zv = *(const float2*)(pb + nt * 8 * LDK + kb);
            bf[nt][0] = __float_as_uint(zv.x); bf[nt][1] = __float_as_uint(zv.y);
        }
#pragma unroll
        for (int mt = 0; mt < 2; ++mt)
#pragma unroll
            for (int nt = 0; nt < 4; ++nt)
                mma_tf32(acc[mt][nt], af[mt], bf[nt]);
    }
}

#define BARG() asm volatile("bar.sync %0, 64;" :: "r"(grp + 1) : "memory")

// =====================================================================
// Edge kernel: 4 independent 2-warp groups (m32n64 per warp);
// register-prefetched A tiles.
// agg += scatter( ssp(ssp(dijk@W1+b1)@W2+b2) * xf[idx_j] )
// =====================================================================
extern "C" __global__ void __launch_bounds__(256, 1)
k_edges_mma(const float* __restrict__ dijk,
            const int* __restrict__ idx_j,
            const int* __restrict__ seg_i,
            const int* __restrict__ seg_j,
            const float* __restrict__ b1, const float* __restrict__ b2,
            int ne, int ntt) {
    float* sA0 = (float*)dynsmem;                 // NG x (32 x LDK)
    float* sB1 = sA0 + NG * TME * LDK;            // W1t 128 x LDK
    float* sB2 = sB1 + 128 * LDK;                 // W2t 128 x LDK
    int*   sg  = (int*)(sB2 + 128 * LDK);         // [NG][64] gather
    float* sb1 = (float*)(sg + NG * 64);          // bias1 [128]
    float* sb2 = sb1 + 128;                       // bias2 [128]

    const int tid = threadIdx.x;
    const int grp = tid >> 6, gt = tid & 63;      // 4 groups of 64 threads
    const int lane = tid & 31;
    const int g = lane >> 2, c = lane & 3;
    const int nw = (gt >> 5) * 64;                // warp col-half (0 or 64)
    const int pe = ((c & 1) << 2) + (c >> 1);     // phys pos of logical col 2c within octet
    const int po = pe + 2;

    float* sA  = sA0 + grp * TME * LDK;
    int* s_aj = sg + grp * 64;
    int* s_ti = s_aj + TME;

    if (tid < 128) sb1[tid] = b1[tid];
    else sb2[tid - 128] = b2[tid - 128];

    load_w_tile(sB1, g_W1t, tid, 256);
    load_w_tile(sB2, g_W2t, tid, 256);
    __syncthreads();

    const float* pa  = sA  + g * LDK + 2 * c;
    const float* pb1 = sB1 + (nw + g) * LDK + 2 * c;
    const float* pb2 = sB2 + (nw + g) * LDK + 2 * c;

    const int tstride = gridDim.x * NG;
    int t = blockIdx.x * NG + grp;

    // per-thread A mapping for 16 prefetch quads: idx = gt + i*64
    // row = idx>>5 (0..31), c4 = idx&31
    // ---- prologue prefetch for first tile ----
    float4 pf[16];
    int pf_aj = 0, pf_ti = -1;
    {
        int base = t * TME;
#pragma unroll
        for (int i = 0; i < 16; ++i) {
            int idx = gt + i * 64;
            int gr = base + (idx >> 5);
            pf[i] = (t < ntt && gr < ne) ? ((const float4*)dijk)[gr * 32 + (idx & 31)]
                                         : make_float4(0.f, 0.f, 0.f, 0.f);
        }
        if (gt < TME) {
            int e = base + gt;
            if (t < ntt && e < ne) { int p = seg_j[e]; pf_aj = idx_j[p]; pf_ti = seg_i[p]; }
        }
    }

    for (; t < ntt; ) {
        // ---- commit prefetched tile to smem ----
#pragma unroll
        for (int i = 0; i < 16; ++i) {
            int idx = gt + i * 64;
            int row = idx >> 5, c4 = idx & 31;
            float* d = sA + row * LDK + (c4 >> 1) * 8 + (c4 & 1);
            d[0] = to_tf32(pf[i].x); d[2] = to_tf32(pf[i].y);
            d[4] = to_tf32(pf[i].z); d[6] = to_tf32(pf[i].w);
        }
        if (gt < TME) { s_aj[gt] = pf_aj; s_ti[gt] = pf_ti; }
        BARG();

        // ---- issue prefetch for next tile (drains behind the GEMMs) ----
        const int tn = t + tstride;
        {
            int base = tn * TME;
#pragma unroll
            for (int i = 0; i < 16; ++i) {
                int idx = gt + i * 64;
                int gr = base + (idx >> 5);
                pf[i] = (tn < ntt && gr < ne) ? ((const float4*)dijk)[gr * 32 + (idx & 31)]
                                              : make_float4(0.f, 0.f, 0.f, 0.f);
            }
            pf_aj = 0; pf_ti = -1;
            if (gt < TME) {
                int e = base + gt;
                if (tn < ntt && e < ne) { int p = seg_j[e]; pf_aj = idx_j[p]; pf_ti = seg_i[p]; }
            }
        }

        float acc[2][8][4];
        gemm32x64(pa, pb1, acc);
        BARG();

        // epi1: H = tf32(ssp(D + b1)) -> sA
#pragma unroll
        for (int mt = 0; mt < 2; ++mt) {
            int row = mt * 16 + g;
#pragma unroll
            for (int nt = 0; nt < 8; ++nt) {
                int col = nw + nt * 8 + 2 * c;
                float2 bb = *(const float2*)(sb1 + col);
                float* d0 = sA + row * LDK + nw + nt * 8;
                float* d1 = d0 + 8 * LDK;
                d0[pe] = to_tf32(ssp_f(acc[mt][nt][0] + bb.x));
                d0[po] = to_tf32(ssp_f(acc[mt][nt][1] + bb.y));
                d1[pe] = to_tf32(ssp_f(acc[mt][nt][2] + bb.x));
                d1[po] = to_tf32(ssp_f(acc[mt][nt][3] + bb.y));
            }
        }
        BARG();

        gemm32x64(pa, pb2, acc);
        BARG();

        // epi2a: W = ssp(D + b2) -> sA (fp32)
#pragma unroll
        for (int mt = 0; mt < 2; ++mt) {
            int row = mt * 16 + g;
#pragma unroll
            for (int nt = 0; nt < 8; ++nt) {
                int col = nw + nt * 8 + 2 * c;
                float2 bb = *(const float2*)(sb2 + col);
                float* d0 = sA + row * LDK + nw + nt * 8;
                float* d1 = d0 + 8 * LDK;
                d0[pe] = ssp_f(acc[mt][nt][0] + bb.x);
                d0[po] = ssp_f(acc[mt][nt][1] + bb.y);
                d1[pe] = ssp_f(acc[mt][nt][2] + bb.x);
                d1[po] = ssp_f(acc[mt][nt][3] + bb.y);
            }
        }
        BARG();

        // epi2b: msg = W * xf[aj]; run-length reduce over sorted targets
        // each thread handles 2 columns: gt and gt+64
        {
            const int col0 = gt, col1 = gt + 64;
            const int pc0 = (col0 & ~7) + ((col0 & 3) << 1) + ((col0 >> 2) & 1);
            const int pc1 = (col1 & ~7) + ((col1 & 3) << 1) + ((col1 >> 2) & 1);
            float a0 = 0.f, a1 = 0.f;
            int cur = -1;
#pragma unroll
            for (int row = 0; row < TME; ++row) {
                int tgt = s_ti[row];
                const float* xrow = g_xf + (size_t)s_aj[row] * C;
                float wv0 = sA[row * LDK + pc0];
                float wv1 = sA[row * LDK + pc1];
                float xv0 = __ldg(xrow + col0);
                float xv1 = __ldg(xrow + col1);
                if (tgt != cur) {
                    if (cur >= 0) {
                        atomicAdd(&g_agg[(size_t)cur * C + col0], a0);
                        atomicAdd(&g_agg[(size_t)cur * C + col1], a1);
                    }
                    a0 = 0.f; a1 = 0.f; cur = tgt;
                }
                a0 = fmaf(wv0, xv0, a0);
                a1 = fmaf(wv1, xv1, a1);
            }
            if (cur >= 0) {
                atomicAdd(&g_agg[(size_t)cur * C + col0], a0);
                atomicAdd(&g_agg[(size_t)cur * C + col1], a1);
            }
        }
        BARG();
        t = tn;
    }
}

// =====================================================================
// k_xf: xf = x @ Wi (tf32 mma), also zeroes g_agg rows of this tile
// =====================================================================
extern "C" __global__ void __launch_bounds__(512, 1)
k_xf_mma(const float* __restrict__ x, int na) {
    float* sA = (float*)dynsmem;        // 128 x LDK
    float* sB = sA + 128 * LDK;         // Wit
    const int tid = threadIdx.x, wid = tid >> 5, lane = tid & 31;
    const int g = lane >> 2, c = lane & 3;
    const int mr = (wid & 3) * 32, nc = (wid >> 2) * 32;
    const int base = blockIdx.x * 128;

    for (int idx = tid; idx < 128 * 32; idx += 512) {
        int row = idx >> 5, c4 = idx & 31;
        int gr = base + row;
        if (gr < na) ((float4*)(g_agg + (size_t)gr * C))[c4] = make_float4(0.f, 0.f, 0.f, 0.f);
    }
    load_w_tile(sB, g_Wit, tid, 512);
    load_a_tile(sA, x, base, na, 128, tid, 512);
    __syncthreads();

    float acc[2][4][4];
    gemm32x32(sA + (mr + g) * LDK + 2 * c, sB + (nc + g) * LDK + 2 * c, acc);

#pragma unroll
    for (int mt = 0; mt < 2; ++mt)
#pragma unroll
        for (int half = 0; half < 2; ++half) {
            int r = base + mr + mt * 16 + half * 8 + g;
            if (r < na) {
#pragma unroll
                for (int nt = 0; nt < 4; ++nt) {
                    int col = nc + nt * 8 + 2 * c;
                    float2 v = make_float2(acc[mt][nt][half * 2], acc[mt][nt][half * 2 + 1]);
                    *(float2*)(&g_xf[(size_t)r * C + col]) = v;
                }
            }
        }
}

// =====================================================================
// k_out: h = ssp(agg@Wo+bo); v = h@Wd+bd; y = x+v; writes (y, v)
// =====================================================================
extern "C" __global__ void __launch_bounds__(512, 1)
k_out_mma(const float* __restrict__ x,
          const float* __restrict__ bo, const float* __restrict__ bd,
          float* __restrict__ out_y, float* __restrict__ out_v, int na) {
    float* sA  = (float*)dynsmem;       // 128 x LDK
    float* sBo = sA + 128 * LDK;        // Wot
    float* sBd = sBo + 128 * LDK;       // Wdt
    const int tid = threadIdx.x, wid = tid >> 5, lane = tid & 31;
    const int g = lane >> 2, c = lane & 3;
    const int mr = (wid & 3) * 32, nc = (wid >> 2) * 32;
    const int pe = ((c & 1) << 2) + (c >> 1);
    const int po = pe + 2;
    const int base = blockIdx.x * 128;

    float boe[4], boo[4], bde[4], bdo[4];
#pragma unroll
    for (int nt = 0; nt < 4; ++nt) {
        int col = nc + nt * 8 + 2 * c;
        boe[nt] = bo[col]; boo[nt] = bo[col + 1];
        bde[nt] = bd[col]; bdo[nt] = bd[col + 1];
    }

    load_w_tile(sBo, g_Wot, tid, 512);
    load_w_tile(sBd, g_Wdt, tid, 512);
    load_a_tile(sA, g_agg, base, na, 128, tid, 512);
    __syncthreads();

    const float* pa = sA + (mr + g) * LDK + 2 * c;
    float acc[2][4][4];
    gemm32x32(pa, sBo + (nc + g) * LDK + 2 * c, acc);
    __syncthreads();   // all warps done reading sA

    // epi1: H = tf32(ssp(D + bo)) -> sA
#pragma unroll
    for (int mt = 0; mt < 2; ++mt) {
        int row = mr + mt * 16 + g;
#pragma unroll
        for (int nt = 0; nt < 4; ++nt) {
            float* d0 = sA + row * LDK + nc + nt * 8;
            float* d1 = d0 + 8 * LDK;
            d0[pe] = to_tf32(ssp_f(acc[mt][nt][0] + boe[nt]));
            d0[po] = to_tf32(ssp_f(acc[mt][nt][1] + boo[nt]));
            d1[pe] = to_tf32(ssp_f(acc[mt][nt][2] + boe[nt]));
            d1[po] = to_tf32(ssp_f(acc[mt][nt][3] + boo[nt]));
        }
    }
    __syncthreads();

    gemm32x32(pa, sBd + (nc + g) * LDK + 2 * c, acc);

    // final epilogue: v = D + bd; y = x + v
#pragma unroll
    for (int mt = 0; mt < 2; ++mt)
#pragma unroll
        for (int half = 0; half < 2; ++half) {
            int r = base + mr + mt * 16 + half * 8 + g;
            if (r < na) {
#pragma unroll
                for (int nt = 0; nt < 4; ++nt) {
                    int col = nc + nt * 8 + 2 * c;
                    float vx = acc[mt][nt][half * 2]     + bde[nt];
                    float vy = acc[mt][nt][half * 2 + 1] + bdo[nt];
                    float2 xv = *(const float2*)(&x[(size_t)r * C + col]);
                    *(float2*)(&out_v[(size_t)r * C + col]) = make_float2(vx, vy);
                    *(float2*)(&out_y[(size_t)r * C + col]) = make_float2(xv.x + vx, xv.y + vy);
                }
            }
        }
}

// ---------------- transpose 5 weights W[k][n] -> Wt[n][k] ----------------
extern "C" __global__ void k_tr5(const float* __restrict__ s0, const float* __restrict__ s1,
                                 const float* __restrict__ s2, const float* __restrict__ s3,
                                 const float* __restrict__ s4) {
    __shared__ float t[32][33];
    const float* s; float* d;
    switch (blockIdx.z) {
        case 0: s = s0; d = g_W1t; break;
        case 1: s = s1; d = g_W2t; break;
        case 2: s = s2; d = g_Wit; break;
        case 3: s = s3; d = g_Wot; break;
        default: s = s4; d = g_Wdt; break;
    }
    int bx = blockIdx.x, by = blockIdx.y;
    int xx = threadIdx.x, yy = threadIdx.y;
#pragma unroll
    for (int i = 0; i < 32; i += 8) t[yy + i][xx] = s[(by * 32 + yy + i) * C + bx * 32 + xx];
    __syncthreads();
#pragma unroll
    for (int i = 0; i < 32; i += 8) d[(bx * 32 + yy + i) * C + by * 32 + xx] = t[xx][yy + i];
}

// ============================ launch ============================
extern "C" void kernel_launch(void* const* d_in, const int* in_sizes, int n_in,
                              void* d_out, int out_size) {
    const float* x    = (const float*)d_in[0];
    const float* dijk = (const float*)d_in[1];
    const int*   idxj = (const int*)d_in[2];
    const int*   segi = (const int*)d_in[3];
    const int*   segj = (const int*)d_in[4];
    const float* W1   = (const float*)d_in[5];
    const float* b1   = (const float*)d_in[6];
    const float* W2   = (const float*)d_in[7];
    const float* b2   = (const float*)d_in[8];
    const float* Wi   = (const float*)d_in[9];
    const float* Wo   = (const float*)d_in[10];
    const float* bo   = (const float*)d_in[11];
    const float* Wd   = (const float*)d_in[12];
    const float* bd   = (const float*)d_in[13];

    int na = in_sizes[0] / C;
    int ne = in_sizes[2];
    int ntt = (ne + TME - 1) / TME;
    int g_atoms = (na + 127) / 128;

    float* out_y = (float*)d_out;
    float* out_v = out_y + (size_t)na * C;

    const int SM_XF   = 2 * 128 * LDK * 4;                          // 139264
    const int SM_OUT  = 3 * 128 * LDK * 4;                          // 208896
    const int SM_EDGE = (NG * TME + 2 * 128) * LDK * 4 + 2048;      // 210944

    cudaFuncSetAttribute(k_xf_mma,    cudaFuncAttributeMaxDynamicSharedMemorySize, SM_XF);
    cudaFuncSetAttribute(k_out_mma,   cudaFuncAttributeMaxDynamicSharedMemorySize, SM_OUT);
    cudaFuncSetAttribute(k_edges_mma, cudaFuncAttributeMaxDynamicSharedMemorySize, SM_EDGE);

    k_tr5<<<dim3(4, 4, 5), dim3(32, 8)>>>(W1, W2, Wi, Wo, Wd);
    k_xf_mma<<<g_atoms, 512, SM_XF>>>(x, na);
    k_edges_mma<<<148, 256, SM_EDGE>>>(dijk, idxj, segi, segj, b1, b2, ne, ntt);
    k_out_mma<<<g_atoms, 512, SM_OUT>>>(x, bo, bd, out_y, out_v, na);
}

// round 12
// speedup vs baseline: 1.1313x; 1.1313x over previous
#include <cuda_runtime.h>
#include <cstdint>

#define C   128
#define LDK 136   // smem row stride (floats): 8-bank stride => conflict-free LDS.64
#define TME 32    // edge tile rows per group
#define NG  4     // independent warp-groups per CTA (edge)

extern __shared__ char dynsmem[];

// ---------------- scratch (device globals; allocation-free rule) ----------------
static __device__ __align__(16) float g_xf[20480 * C];
static __device__ __align__(16) float g_agg[20480 * C];
static __device__ __align__(16) float g_W1t[C * C];
static __device__ __align__(16) float g_W2t[C * C];
static __device__ __align__(16) float g_Wit[C * C];
static __device__ __align__(16) float g_Wot[C * C];
static __device__ __align__(16) float g_Wdt[C * C];

__device__ __forceinline__ float ssp_f(float x) {
    float t = __expf(-fabsf(x));
    return fmaxf(x, 0.0f) + __logf(1.0f + t) - 0.693147180559945f;
}

__device__ __forceinline__ float to_tf32(float x) {
    uint32_t u;
    asm("cvt.rna.tf32.f32 %0, %1;" : "=r"(u) : "f"(x));
    return __uint_as_float(u);
}

__device__ __forceinline__ void mma_tf32(float* d, const uint32_t* a, const uint32_t* b) {
    asm volatile(
        "mma.sync.aligned.m16n8k8.row.col.f32.tf32.tf32.f32 "
        "{%0,%1,%2,%3}, {%4,%5,%6,%7}, {%8,%9}, {%0,%1,%2,%3};"
        : "+f"(d[0]), "+f"(d[1]), "+f"(d[2]), "+f"(d[3])
        : "r"(a[0]), "r"(a[1]), "r"(a[2]), "r"(a[3]), "r"(b[0]), "r"(b[1]));
}

// Octet k-interleave: logical k j8 -> phys ((j8&3)<<1)|(j8>>2); pair {2c,2c+1} is one LDS.64.

__device__ __forceinline__ void load_w_tile(float* dst, const float* __restrict__ src,
                                            int tid, int nthr) {
    for (int idx = tid; idx < 128 * 32; idx += nthr) {
        int row = idx >> 5, c4 = idx & 31;
        float4 v = ((const float4*)src)[idx];
        float* d = dst + row * LDK + (c4 >> 1) * 8 + (c4 & 1);
        d[0] = to_tf32(v.x); d[2] = to_tf32(v.y); d[4] = to_tf32(v.z); d[6] = to_tf32(v.w);
    }
}

__device__ __forceinline__ void load_a_tile(float* dst, const float* __restrict__ src,
                                            int base, int nrow_total, int rows,
                                            int tid, int nthr) {
    for (int idx = tid; idx < rows * 32; idx += nthr) {
        int row = idx >> 5, c4 = idx & 31;
        float4 v = make_float4(0.f, 0.f, 0.f, 0.f);
        int gr = base + row;
        if (gr < nrow_total) v = ((const float4*)src)[gr * 32 + c4];
        float* d = dst + row * LDK + (c4 >> 1) * 8 + (c4 & 1);
        d[0] = to_tf32(v.x); d[2] = to_tf32(v.y); d[4] = to_tf32(v.z); d[6] = to_tf32(v.w);
    }
}

// one warp's 32x32 output tile over k=128
__device__ __forceinline__ void gemm32x32(const float* pa, const float* pb, float acc[2][4][4]) {
#pragma unroll
    for (int mt = 0; mt < 2; ++mt)
#pragma unroll
        for (int nt = 0; nt < 4; ++nt)
#pragma unroll
            for (int q = 0; q < 4; ++q) acc[mt][nt][q] = 0.f;
#pragma unroll
    for (int kk = 0; kk < 16; ++kk) {
        const int kb = kk * 8;
        uint32_t af[2][4], bf[4][2];
#pragma unroll
        for (int mt = 0; mt < 2; ++mt) {
            float2 xv = *(const float2*)(pa + mt * 16 * LDK + kb);
            float2 yv = *(const float2*)(pa + (mt * 16 + 8) * LDK + kb);
            af[mt][0] = __float_as_uint(xv.x); af[mt][2] = __float_as_uint(xv.y);
            af[mt][1] = __float_as_uint(yv.x); af[mt][3] = __float_as_uint(yv.y);
        }
#pragma unroll
        for (int nt = 0; nt < 4; ++nt) {
            float2 zv = *(const float2*)(pb + nt * 8 * LDK + kb);
            bf[nt][0] = __float_as_uint(zv.x); bf[nt][1] = __float_as_uint(zv.y);
        }
#pragma unroll
        for (int mt = 0; mt < 2; ++mt)
#pragma unroll
            for (int nt = 0; nt < 4; ++nt)
                mma_tf32(acc[mt][nt], af[mt], bf[nt]);
    }
}

#define BARG() asm volatile("bar.sync %0, 128;" :: "r"(grp + 1) : "memory")
#define BARO() asm volatile("bar.sync %0, 256;" :: "r"(grp + 1) : "memory")

// =====================================================================
// Edge kernel (R10 config): 4 independent 4-warp groups; register-
// prefetched A tiles.  agg += scatter(ssp(ssp(dijk@W1+b1)@W2+b2)*xf[idx_j])
// =====================================================================
extern "C" __global__ void __launch_bounds__(512, 1)
k_edges_mma(const float* __restrict__ dijk,
            const int* __restrict__ idx_j,
            const int* __restrict__ seg_i,
            const int* __restrict__ seg_j,
            const float* __restrict__ b1, const float* __restrict__ b2,
            int ne, int ntt) {
    float* sA0 = (float*)dynsmem;                 // NG x (32 x LDK)
    float* sB1 = sA0 + NG * TME * LDK;            // W1t 128 x LDK
    float* sB2 = sB1 + 128 * LDK;                 // W2t 128 x LDK
    int*   sg  = (int*)(sB2 + 128 * LDK);         // [NG][64] gather
    float* sb1 = (float*)(sg + NG * 64);          // bias1 [128]
    float* sb2 = sb1 + 128;                       // bias2 [128]

    const int tid = threadIdx.x;
    const int grp = tid >> 7, gt = tid & 127;     // 4 groups of 128 threads
    const int wid = gt >> 5, lane = tid & 31;
    const int g = lane >> 2, c = lane & 3;
    const int nc = wid * 32;                      // warp col-block (mr = 0 for all)
    const int pe = ((c & 1) << 2) + (c >> 1);     // phys pos of logical col 2c within octet
    const int po = pe + 2;

    float* sA  = sA0 + grp * TME * LDK;
    int* s_aj = sg + grp * 64;
    int* s_ti = s_aj + TME;

    if (tid < 128) sb1[tid] = b1[tid];
    else if (tid < 256) sb2[tid - 128] = b2[tid - 128];

    load_w_tile(sB1, g_W1t, tid, 512);
    load_w_tile(sB2, g_W2t, tid, 512);
    __syncthreads();

    const float* pa  = sA  + g * LDK + 2 * c;
    const float* pb1 = sB1 + (nc + g) * LDK + 2 * c;
    const float* pb2 = sB2 + (nc + g) * LDK + 2 * c;

    const int tstride = gridDim.x * NG;
    int t = blockIdx.x * NG + grp;

    // per-thread A-row mapping for the 8 prefetch quads
    const int prow = gt >> 5;        // base row (advances by 4 per quad)
    const int pc4  = gt & 31;

    // ---- prologue prefetch for first tile ----
    float4 pf[8];
    int pf_aj = 0, pf_ti = -1;
    {
        int base = t * TME;
#pragma unroll
        for (int i = 0; i < 8; ++i) {
            int gr = base + prow + i * 4;
            pf[i] = (t < ntt && gr < ne) ? ((const float4*)dijk)[gr * 32 + pc4]
                                         : make_float4(0.f, 0.f, 0.f, 0.f);
        }
        if (gt < TME) {
            int e = base + gt;
            if (t < ntt && e < ne) { int p = seg_j[e]; pf_aj = idx_j[p]; pf_ti = seg_i[p]; }
        }
    }

    for (; t < ntt; ) {
        // ---- commit prefetched tile to smem ----
#pragma unroll
        for (int i = 0; i < 8; ++i) {
            int row = prow + i * 4;
            float* d = sA + row * LDK + (pc4 >> 1) * 8 + (pc4 & 1);
            d[0] = to_tf32(pf[i].x); d[2] = to_tf32(pf[i].y);
            d[4] = to_tf32(pf[i].z); d[6] = to_tf32(pf[i].w);
        }
        if (gt < TME) { s_aj[gt] = pf_aj; s_ti[gt] = pf_ti; }
        BARG();

        // ---- issue prefetch for next tile (drains behind the GEMMs) ----
        const int tn = t + tstride;
        {
            int base = tn * TME;
#pragma unroll
            for (int i = 0; i < 8; ++i) {
                int gr = base + prow + i * 4;
                pf[i] = (tn < ntt && gr < ne) ? ((const float4*)dijk)[gr * 32 + pc4]
                                              : make_float4(0.f, 0.f, 0.f, 0.f);
            }
            pf_aj = 0; pf_ti = -1;
            if (gt < TME) {
                int e = base + gt;
                if (tn < ntt && e < ne) { int p = seg_j[e]; pf_aj = idx_j[p]; pf_ti = seg_i[p]; }
            }
        }

        float acc[2][4][4];
        gemm32x32(pa, pb1, acc);
        BARG();

        // epi1: H = tf32(ssp(D + b1)) -> sA
#pragma unroll
        for (int mt = 0; mt < 2; ++mt) {
            int row = mt * 16 + g;
#pragma unroll
            for (int nt = 0; nt < 4; ++nt) {
                int col = nc + nt * 8 + 2 * c;
                float2 bb = *(const float2*)(sb1 + col);
                float* d0 = sA + row * LDK + nc + nt * 8;
                float* d1 = d0 + 8 * LDK;
                d0[pe] = to_tf32(ssp_f(acc[mt][nt][0] + bb.x));
                d0[po] = to_tf32(ssp_f(acc[mt][nt][1] + bb.y));
                d1[pe] = to_tf32(ssp_f(acc[mt][nt][2] + bb.x));
                d1[po] = to_tf32(ssp_f(acc[mt][nt][3] + bb.y));
            }
        }
        BARG();

        gemm32x32(pa, pb2, acc);
        BARG();

        // epi2a: W = ssp(D + b2) -> sA (fp32)
#pragma unroll
        for (int mt = 0; mt < 2; ++mt) {
            int row = mt * 16 + g;
#pragma unroll
            for (int nt = 0; nt < 4; ++nt) {
                int col = nc + nt * 8 + 2 * c;
                float2 bb = *(const float2*)(sb2 + col);
                float* d0 = sA + row * LDK + nc + nt * 8;
                float* d1 = d0 + 8 * LDK;
                d0[pe] = ssp_f(acc[mt][nt][0] + bb.x);
                d0[po] = ssp_f(acc[mt][nt][1] + bb.y);
                d1[pe] = ssp_f(acc[mt][nt][2] + bb.x);
                d1[po] = ssp_f(acc[mt][nt][3] + bb.y);
            }
        }
        BARG();

        // epi2b: msg = W * xf[aj]; run-length reduce over sorted targets
        {
            const int col = gt;
            const int pc = (col & ~7) + ((col & 3) << 1) + ((col >> 2) & 1);
            float acc1 = 0.f;
            int cur = -1;
#pragma unroll
            for (int row = 0; row < TME; ++row) {
                int tgt = s_ti[row];
                float wv = sA[row * LDK + pc];
                float xv = __ldg(&g_xf[(size_t)s_aj[row] * C + col]);
                if (tgt != cur) {
                    if (cur >= 0) atomicAdd(&g_agg[(size_t)cur * C + col], acc1);
                    acc1 = 0.f; cur = tgt;
                }
                acc1 = fmaf(wv, xv, acc1);
            }
            if (cur >= 0) atomicAdd(&g_agg[(size_t)cur * C + col], acc1);
        }
        BARG();
        t = tn;
    }
}

// =====================================================================
// k_xf: xf = x @ Wi (tf32 mma), also zeroes g_agg rows of this tile
// =====================================================================
extern "C" __global__ void __launch_bounds__(512, 1)
k_xf_mma(const float* __restrict__ x, int na) {
    float* sA = (float*)dynsmem;        // 128 x LDK
    float* sB = sA + 128 * LDK;         // Wit
    const int tid = threadIdx.x, wid = tid >> 5, lane = tid & 31;
    const int g = lane >> 2, c = lane & 3;
    const int mr = (wid & 3) * 32, nc = (wid >> 2) * 32;
    const int base = blockIdx.x * 128;

    // zero agg first so the STGs overlap the loads below
    for (int idx = tid; idx < 128 * 32; idx += 512) {
        int row = idx >> 5, c4 = idx & 31;
        int gr = base + row;
        if (gr < na) ((float4*)(g_agg + (size_t)gr * C))[c4] = make_float4(0.f, 0.f, 0.f, 0.f);
    }
    load_a_tile(sA, x, base, na, 128, tid, 512);
    load_w_tile(sB, g_Wit, tid, 512);
    __syncthreads();

    float acc[2][4][4];
    gemm32x32(sA + (mr + g) * LDK + 2 * c, sB + (nc + g) * LDK + 2 * c, acc);

#pragma unroll
    for (int mt = 0; mt < 2; ++mt)
#pragma unroll
        for (int half = 0; half < 2; ++half) {
            int r = base + mr + mt * 16 + half * 8 + g;
            if (r < na) {
#pragma unroll
                for (int nt = 0; nt < 4; ++nt) {
                    int col = nc + nt * 8 + 2 * c;
                    float2 v = make_float2(acc[mt][nt][half * 2], acc[mt][nt][half * 2 + 1]);
                    *(float2*)(&g_xf[(size_t)r * C + col]) = v;
                }
            }
        }
}

// =====================================================================
// k_out: h = ssp(agg@Wo+bo); v = h@Wd+bd; y = x+v; writes (y, v)
// 2 independent 8-warp groups of 64 rows each (named barriers).
// =====================================================================
extern "C" __global__ void __launch_bounds__(512, 1)
k_out_mma(const float* __restrict__ x,
          const float* __restrict__ bo, const float* __restrict__ bd,
          float* __restrict__ out_y, float* __restrict__ out_v, int na) {
    float* sA0 = (float*)dynsmem;       // 2 x (64 x LDK)
    float* sBo = sA0 + 128 * LDK;       // Wot
    float* sBd = sBo + 128 * LDK;       // Wdt
    const int tid = threadIdx.x;
    const int grp = tid >> 8, gt = tid & 255;     // 2 groups of 256 threads
    const int wid = gt >> 5, lane = tid & 31;
    const int g = lane >> 2, c = lane & 3;
    const int mr = (wid & 1) * 32, nc = (wid >> 1) * 32;
    const int pe = ((c & 1) << 2) + (c >> 1);
    const int po = pe + 2;
    const int base = blockIdx.x * 128 + grp * 64;

    float* sA = sA0 + grp * 64 * LDK;

    float boe[4], boo[4], bde[4], bdo[4];
#pragma unroll
    for (int nt = 0; nt < 4; ++nt) {
        int col = nc + nt * 8 + 2 * c;
        boe[nt] = bo[col]; boo[nt] = bo[col + 1];
        bde[nt] = bd[col]; bdo[nt] = bd[col + 1];
    }

    load_a_tile(sA, g_agg, base, na, 64, gt, 256);
    load_w_tile(sBo, g_Wot, tid, 512);
    load_w_tile(sBd, g_Wdt, tid, 512);
    __syncthreads();

    const float* pa = sA + (mr + g) * LDK + 2 * c;
    float acc[2][4][4];
    gemm32x32(pa, sBo + (nc + g) * LDK + 2 * c, acc);
    BARO();   // group's warps done reading its sA

    // epi1: H = tf32(ssp(D + bo)) -> sA
#pragma unroll
    for (int mt = 0; mt < 2; ++mt) {
        int row = mr + mt * 16 + g;
#pragma unroll
        for (int nt = 0; nt < 4; ++nt) {
            float* d0 = sA + row * LDK + nc + nt * 8;
            float* d1 = d0 + 8 * LDK;
            d0[pe] = to_tf32(ssp_f(acc[mt][nt][0] + boe[nt]));
            d0[po] = to_tf32(ssp_f(acc[mt][nt][1] + boo[nt]));
            d1[pe] = to_tf32(ssp_f(acc[mt][nt][2] + boe[nt]));
            d1[po] = to_tf32(ssp_f(acc[mt][nt][3] + boo[nt]));
        }
    }
    BARO();

    gemm32x32(pa, sBd + (nc + g) * LDK + 2 * c, acc);

    // final epilogue: v = D + bd; y = x + v
#pragma unroll
    for (int mt = 0; mt < 2; ++mt)
#pragma unroll
        for (int half = 0; half < 2; ++half) {
            int r = base + mr + mt * 16 + half * 8 + g;
            if (r < na) {
#pragma unroll
                for (int nt = 0; nt < 4; ++nt) {
                    int col = nc + nt * 8 + 2 * c;
                    float vx = acc[mt][nt][half * 2]     + bde[nt];
                    float vy = acc[mt][nt][half * 2 + 1] + bdo[nt];
                    float2 xv = *(const float2*)(&x[(size_t)r * C + col]);
                    *(float2*)(&out_v[(size_t)r * C + col]) = make_float2(vx, vy);
                    *(float2*)(&out_y[(size_t)r * C + col]) = make_float2(xv.x + vx, xv.y + vy);
                }
            }
        }
}

// ---------------- transpose 5 weights W[k][n] -> Wt[n][k] ----------------
extern "C" __global__ void k_tr5(const float* __restrict__ s0, const float* __restrict__ s1,
                                 const float* __restrict__ s2, const float* __restrict__ s3,
                                 const float* __restrict__ s4) {
    __shared__ float t[32][33];
    const float* s; float* d;
    switch (blockIdx.z) {
        case 0: s = s0; d = g_W1t; break;
        case 1: s = s1; d = g_W2t; break;
        case 2: s = s2; d = g_Wit; break;
        case 3: s = s3; d = g_Wot; break;
        default: s = s4; d = g_Wdt; break;
    }
    int bx = blockIdx.x, by = blockIdx.y;
    int xx = threadIdx.x, yy = threadIdx.y;
#pragma unroll
    for (int i = 0; i < 32; i += 8) t[yy + i][xx] = s[(by * 32 + yy + i) * C + bx * 32 + xx];
    __syncthreads();
#pragma unroll
    for (int i = 0; i < 32; i += 8) d[(bx * 32 + yy + i) * C + by * 32 + xx] = t[xx][yy + i];
}

// ============================ launch ============================
extern "C" void kernel_launch(void* const* d_in, const int* in_sizes, int n_in,
                              void* d_out, int out_size) {
    const float* x    = (const float*)d_in[0];
    const float* dijk = (const float*)d_in[1];
    const int*   idxj = (const int*)d_in[2];
    const int*   segi = (const int*)d_in[3];
    const int*   segj = (const int*)d_in[4];
    const float* W1   = (const float*)d_in[5];
    const float* b1   = (const float*)d_in[6];
    const float* W2   = (const float*)d_in[7];
    const float* b2   = (const float*)d_in[8];
    const float* Wi   = (const float*)d_in[9];
    const float* Wo   = (const float*)d_in[10];
    const float* bo   = (const float*)d_in[11];
    const float* Wd   = (const float*)d_in[12];
    const float* bd   = (const float*)d_in[13];

    int na = in_sizes[0] / C;
    int ne = in_sizes[2];
    int ntt = (ne + TME - 1) / TME;
    int g_atoms = (na + 127) / 128;

    float* out_y = (float*)d_out;
    float* out_v = out_y + (size_t)na * C;

    const int SM_XF   = 2 * 128 * LDK * 4;                          // 139264
    const int SM_OUT  = 3 * 128 * LDK * 4;                          // 208896
    const int SM_EDGE = (NG * TME + 2 * 128) * LDK * 4 + 2048;      // 210944

    cudaFuncSetAttribute(k_xf_mma,    cudaFuncAttributeMaxDynamicSharedMemorySize, SM_XF);
    cudaFuncSetAttribute(k_out_mma,   cudaFuncAttributeMaxDynamicSharedMemorySize, SM_OUT);
    cudaFuncSetAttribute(k_edges_mma, cudaFuncAttributeMaxDynamicSharedMemorySize, SM_EDGE);

    k_tr5<<<dim3(4, 4, 5), dim3(32, 8)>>>(W1, W2, Wi, Wo, Wd);
    k_xf_mma<<<g_atoms, 512, SM_XF>>>(x, na);
    k_edges_mma<<<148, 512, SM_EDGE>>>(dijk, idxj, segi, segj, b1, b2, ne, ntt);
    k_out_mma<<<g_atoms, 512, SM_OUT>>>(x, bo, bd, out_y, out_v, na);
}

// round 13
// speedup vs baseline: 1.1588x; 1.0242x over previous
#include <cuda_runtime.h>
#include <cstdint>

#define C   128
#define LDK 136   // smem row stride (floats): 8-bank stride => conflict-free LDS.64
#define TME 32    // edge tile rows per group
#define NG  4     // independent warp-groups per CTA (edge)

extern __shared__ char dynsmem[];

// ---------------- scratch (device globals; allocation-free rule) ----------------
static __device__ __align__(16) float g_xf[20480 * C];
static __device__ __align__(16) float g_agg[20480 * C];
static __device__ __align__(16) float g_W1t[C * C];
static __device__ __align__(16) float g_W2t[C * C];
static __device__ __align__(16) float g_Wit[C * C];
static __device__ __align__(16) float g_Wot[C * C];
static __device__ __align__(16) float g_Wdt[C * C];

__device__ __forceinline__ float ssp_f(float x) {
    float t = __expf(-fabsf(x));
    return fmaxf(x, 0.0f) + __logf(1.0f + t) - 0.693147180559945f;
}

__device__ __forceinline__ float to_tf32(float x) {
    uint32_t u;
    asm("cvt.rna.tf32.f32 %0, %1;" : "=r"(u) : "f"(x));
    return __uint_as_float(u);
}

__device__ __forceinline__ void mma_tf32(float* d, const uint32_t* a, const uint32_t* b) {
    asm volatile(
        "mma.sync.aligned.m16n8k8.row.col.f32.tf32.tf32.f32 "
        "{%0,%1,%2,%3}, {%4,%5,%6,%7}, {%8,%9}, {%0,%1,%2,%3};"
        : "+f"(d[0]), "+f"(d[1]), "+f"(d[2]), "+f"(d[3])
        : "r"(a[0]), "r"(a[1]), "r"(a[2]), "r"(a[3]), "r"(b[0]), "r"(b[1]));
}

// Octet k-interleave: logical k j8 -> phys ((j8&3)<<1)|(j8>>2); pair {2c,2c+1} is one LDS.64.

__device__ __forceinline__ void load_w_tile(float* dst, const float* __restrict__ src,
                                            int tid, int nthr) {
    for (int idx = tid; idx < 128 * 32; idx += nthr) {
        int row = idx >> 5, c4 = idx & 31;
        float4 v = ((const float4*)src)[idx];
        float* d = dst + row * LDK + (c4 >> 1) * 8 + (c4 & 1);
        d[0] = to_tf32(v.x); d[2] = to_tf32(v.y); d[4] = to_tf32(v.z); d[6] = to_tf32(v.w);
    }
}

__device__ __forceinline__ void load_a_tile(float* dst, const float* __restrict__ src,
                                            int base, int nrow_total, int rows,
                                            int tid, int nthr) {
    for (int idx = tid; idx < rows * 32; idx += nthr) {
        int row = idx >> 5, c4 = idx & 31;
        float4 v = make_float4(0.f, 0.f, 0.f, 0.f);
        int gr = base + row;
        if (gr < nrow_total) v = ((const float4*)src)[gr * 32 + c4];
        float* d = dst + row * LDK + (c4 >> 1) * 8 + (c4 & 1);
        d[0] = to_tf32(v.x); d[2] = to_tf32(v.y); d[4] = to_tf32(v.z); d[6] = to_tf32(v.w);
    }
}

// one warp's 32x32 output tile over k=128
__device__ __forceinline__ void gemm32x32(const float* pa, const float* pb, float acc[2][4][4]) {
#pragma unroll
    for (int mt = 0; mt < 2; ++mt)
#pragma unroll
        for (int nt = 0; nt < 4; ++nt)
#pragma unroll
            for (int q = 0; q < 4; ++q) acc[mt][nt][q] = 0.f;
#pragma unroll
    for (int kk = 0; kk < 16; ++kk) {
        const int kb = kk * 8;
        uint32_t af[2][4], bf[4][2];
#pragma unroll
        for (int mt = 0; mt < 2; ++mt) {
            float2 xv = *(const float2*)(pa + mt * 16 * LDK + kb);
            float2 yv = *(const float2*)(pa + (mt * 16 + 8) * LDK + kb);
            af[mt][0] = __float_as_uint(xv.x); af[mt][2] = __float_as_uint(xv.y);
            af[mt][1] = __float_as_uint(yv.x); af[mt][3] = __float_as_uint(yv.y);
        }
#pragma unroll
        for (int nt = 0; nt < 4; ++nt) {
            float2 zv = *(const float2*)(pb + nt * 8 * LDK + kb);
            bf[nt][0] = __float_as_uint(zv.x); bf[nt][1] = __float_as_uint(zv.y);
        }
#pragma unroll
        for (int mt = 0; mt < 2; ++mt)
#pragma unroll
            for (int nt = 0; nt < 4; ++nt)
                mma_tf32(acc[mt][nt], af[mt], bf[nt]);
    }
}

#define BARG() asm volatile("bar.sync %0, 128;" :: "r"(grp + 1) : "memory")

// =====================================================================
// Edge kernel (R10 config): 4 independent 4-warp groups; register-
// prefetched A tiles.  agg += scatter(ssp(ssp(dijk@W1+b1)@W2+b2)*xf[idx_j])
// =====================================================================
extern "C" __global__ void __launch_bounds__(512, 1)
k_edges_mma(const float* __restrict__ dijk,
            const int* __restrict__ idx_j,
            const int* __restrict__ seg_i,
            const int* __restrict__ seg_j,
            const float* __restrict__ b1, const float* __restrict__ b2,
            int ne, int ntt) {
    float* sA0 = (float*)dynsmem;                 // NG x (32 x LDK)
    float* sB1 = sA0 + NG * TME * LDK;            // W1t 128 x LDK
    float* sB2 = sB1 + 128 * LDK;                 // W2t 128 x LDK
    int*   sg  = (int*)(sB2 + 128 * LDK);         // [NG][64] gather
    float* sb1 = (float*)(sg + NG * 64);          // bias1 [128]
    float* sb2 = sb1 + 128;                       // bias2 [128]

    const int tid = threadIdx.x;
    const int grp = tid >> 7, gt = tid & 127;     // 4 groups of 128 threads
    const int wid = gt >> 5, lane = tid & 31;
    const int g = lane >> 2, c = lane & 3;
    const int nc = wid * 32;                      // warp col-block (mr = 0 for all)
    const int pe = ((c & 1) << 2) + (c >> 1);     // phys pos of logical col 2c within octet
    const int po = pe + 2;

    float* sA  = sA0 + grp * TME * LDK;
    int* s_aj = sg + grp * 64;
    int* s_ti = s_aj + TME;

    if (tid < 128) sb1[tid] = b1[tid];
    else if (tid < 256) sb2[tid - 128] = b2[tid - 128];

    load_w_tile(sB1, g_W1t, tid, 512);
    load_w_tile(sB2, g_W2t, tid, 512);
    __syncthreads();

    const float* pa  = sA  + g * LDK + 2 * c;
    const float* pb1 = sB1 + (nc + g) * LDK + 2 * c;
    const float* pb2 = sB2 + (nc + g) * LDK + 2 * c;

    const int tstride = gridDim.x * NG;
    int t = blockIdx.x * NG + grp;

    // per-thread A-row mapping for the 8 prefetch quads
    const int prow = gt >> 5;        // base row (advances by 4 per quad)
    const int pc4  = gt & 31;

    // ---- prologue prefetch for first tile ----
    float4 pf[8];
    int pf_aj = 0, pf_ti = -1;
    {
        int base = t * TME;
#pragma unroll
        for (int i = 0; i < 8; ++i) {
            int gr = base + prow + i * 4;
            pf[i] = (t < ntt && gr < ne) ? ((const float4*)dijk)[gr * 32 + pc4]
                                         : make_float4(0.f, 0.f, 0.f, 0.f);
        }
        if (gt < TME) {
            int e = base + gt;
            if (t < ntt && e < ne) { int p = seg_j[e]; pf_aj = idx_j[p]; pf_ti = seg_i[p]; }
        }
    }

    for (; t < ntt; ) {
        // ---- commit prefetched tile to smem ----
#pragma unroll
        for (int i = 0; i < 8; ++i) {
            int row = prow + i * 4;
            float* d = sA + row * LDK + (pc4 >> 1) * 8 + (pc4 & 1);
            d[0] = to_tf32(pf[i].x); d[2] = to_tf32(pf[i].y);
            d[4] = to_tf32(pf[i].z); d[6] = to_tf32(pf[i].w);
        }
        if (gt < TME) { s_aj[gt] = pf_aj; s_ti[gt] = pf_ti; }
        BARG();

        // ---- issue prefetch for next tile (drains behind the GEMMs) ----
        const int tn = t + tstride;
        {
            int base = tn * TME;
#pragma unroll
            for (int i = 0; i < 8; ++i) {
                int gr = base + prow + i * 4;
                pf[i] = (tn < ntt && gr < ne) ? ((const float4*)dijk)[gr * 32 + pc4]
                                              : make_float4(0.f, 0.f, 0.f, 0.f);
            }
            pf_aj = 0; pf_ti = -1;
            if (gt < TME) {
                int e = base + gt;
                if (tn < ntt && e < ne) { int p = seg_j[e]; pf_aj = idx_j[p]; pf_ti = seg_i[p]; }
            }
        }

        float acc[2][4][4];
        gemm32x32(pa, pb1, acc);
        BARG();

        // epi1: H = tf32(ssp(D + b1)) -> sA
#pragma unroll
        for (int mt = 0; mt < 2; ++mt) {
            int row = mt * 16 + g;
#pragma unroll
            for (int nt = 0; nt < 4; ++nt) {
                int col = nc + nt * 8 + 2 * c;
                float2 bb = *(const float2*)(sb1 + col);
                float* d0 = sA + row * LDK + nc + nt * 8;
                float* d1 = d0 + 8 * LDK;
                d0[pe] = to_tf32(ssp_f(acc[mt][nt][0] + bb.x));
                d0[po] = to_tf32(ssp_f(acc[mt][nt][1] + bb.y));
                d1[pe] = to_tf32(ssp_f(acc[mt][nt][2] + bb.x));
                d1[po] = to_tf32(ssp_f(acc[mt][nt][3] + bb.y));
            }
        }
        BARG();

        gemm32x32(pa, pb2, acc);
        BARG();

        // epi2a: W = ssp(D + b2) -> sA (fp32)
#pragma unroll
        for (int mt = 0; mt < 2; ++mt) {
            int row = mt * 16 + g;
#pragma unroll
            for (int nt = 0; nt < 4; ++nt) {
                int col = nc + nt * 8 + 2 * c;
                float2 bb = *(const float2*)(sb2 + col);
                float* d0 = sA + row * LDK + nc + nt * 8;
                float* d1 = d0 + 8 * LDK;
                d0[pe] = ssp_f(acc[mt][nt][0] + bb.x);
                d0[po] = ssp_f(acc[mt][nt][1] + bb.y);
                d1[pe] = ssp_f(acc[mt][nt][2] + bb.x);
                d1[po] = ssp_f(acc[mt][nt][3] + bb.y);
            }
        }
        BARG();

        // epi2b: msg = W * xf[aj]; run-length reduce over sorted targets
        {
            const int col = gt;
            const int pc = (col & ~7) + ((col & 3) << 1) + ((col >> 2) & 1);
            float acc1 = 0.f;
            int cur = -1;
#pragma unroll
            for (int row = 0; row < TME; ++row) {
                int tgt = s_ti[row];
                float wv = sA[row * LDK + pc];
                float xv = __ldg(&g_xf[(size_t)s_aj[row] * C + col]);
                if (tgt != cur) {
                    if (cur >= 0) atomicAdd(&g_agg[(size_t)cur * C + col], acc1);
                    acc1 = 0.f; cur = tgt;
                }
                acc1 = fmaf(wv, xv, acc1);
            }
            if (cur >= 0) atomicAdd(&g_agg[(size_t)cur * C + col], acc1);
        }
        BARG();
        t = tn;
    }
}

// =====================================================================
// k_xf (persistent): xf = x @ Wi (tf32 mma), zeroes g_agg per tile
// =====================================================================
extern "C" __global__ void __launch_bounds__(512, 1)
k_xf_mma(const float* __restrict__ x, int na, int ntiles) {
    float* sA = (float*)dynsmem;        // 128 x LDK
    float* sB = sA + 128 * LDK;         // Wit
    const int tid = threadIdx.x, wid = tid >> 5, lane = tid & 31;
    const int g = lane >> 2, c = lane & 3;
    const int mr = (wid & 3) * 32, nc = (wid >> 2) * 32;

    load_w_tile(sB, g_Wit, tid, 512);

    const float* pa = sA + (mr + g) * LDK + 2 * c;
    const float* pb = sB + (nc + g) * LDK + 2 * c;

    for (int t = blockIdx.x; t < ntiles; t += gridDim.x) {
        const int base = t * 128;

        // zero agg for this tile (overlaps with A load below)
        for (int idx = tid; idx < 128 * 32; idx += 512) {
            int row = idx >> 5, c4 = idx & 31;
            int gr = base + row;
            if (gr < na) ((float4*)(g_agg + (size_t)gr * C))[c4] = make_float4(0.f, 0.f, 0.f, 0.f);
        }
        load_a_tile(sA, x, base, na, 128, tid, 512);
        __syncthreads();

        float acc[2][4][4];
        gemm32x32(pa, pb, acc);

#pragma unroll
        for (int mt = 0; mt < 2; ++mt)
#pragma unroll
            for (int half = 0; half < 2; ++half) {
                int r = base + mr + mt * 16 + half * 8 + g;
                if (r < na) {
#pragma unroll
                    for (int nt = 0; nt < 4; ++nt) {
                        int col = nc + nt * 8 + 2 * c;
                        float2 v = make_float2(acc[mt][nt][half * 2], acc[mt][nt][half * 2 + 1]);
                        *(float2*)(&g_xf[(size_t)r * C + col]) = v;
                    }
                }
            }
        __syncthreads();   // sA reads done before next tile overwrites
    }
}

// =====================================================================
// k_out (persistent): h = ssp(agg@Wo+bo); v = h@Wd+bd; y = x+v
// =====================================================================
extern "C" __global__ void __launch_bounds__(512, 1)
k_out_mma(const float* __restrict__ x,
          const float* __restrict__ bo, const float* __restrict__ bd,
          float* __restrict__ out_y, float* __restrict__ out_v, int na, int ntiles) {
    float* sA  = (float*)dynsmem;       // 128 x LDK
    float* sBo = sA + 128 * LDK;        // Wot
    float* sBd = sBo + 128 * LDK;       // Wdt
    const int tid = threadIdx.x, wid = tid >> 5, lane = tid & 31;
    const int g = lane >> 2, c = lane & 3;
    const int mr = (wid & 3) * 32, nc = (wid >> 2) * 32;
    const int pe = ((c & 1) << 2) + (c >> 1);
    const int po = pe + 2;

    float boe[4], boo[4], bde[4], bdo[4];
#pragma unroll
    for (int nt = 0; nt < 4; ++nt) {
        int col = nc + nt * 8 + 2 * c;
        boe[nt] = bo[col]; boo[nt] = bo[col + 1];
        bde[nt] = bd[col]; bdo[nt] = bd[col + 1];
    }

    load_w_tile(sBo, g_Wot, tid, 512);
    load_w_tile(sBd, g_Wdt, tid, 512);

    const float* pa  = sA + (mr + g) * LDK + 2 * c;
    const float* pbo = sBo + (nc + g) * LDK + 2 * c;
    const float* pbd = sBd + (nc + g) * LDK + 2 * c;

    for (int t = blockIdx.x; t < ntiles; t += gridDim.x) {
        const int base = t * 128;

        load_a_tile(sA, g_agg, base, na, 128, tid, 512);
        __syncthreads();

        float acc[2][4][4];
        gemm32x32(pa, pbo, acc);
        __syncthreads();   // all warps done reading sA

        // epi1: H = tf32(ssp(D + bo)) -> sA
#pragma unroll
        for (int mt = 0; mt < 2; ++mt) {
            int row = mr + mt * 16 + g;
#pragma unroll
            for (int nt = 0; nt < 4; ++nt) {
                float* d0 = sA + row * LDK + nc + nt * 8;
                float* d1 = d0 + 8 * LDK;
                d0[pe] = to_tf32(ssp_f(acc[mt][nt][0] + boe[nt]));
                d0[po] = to_tf32(ssp_f(acc[mt][nt][1] + boo[nt]));
                d1[pe] = to_tf32(ssp_f(acc[mt][nt][2] + boe[nt]));
                d1[po] = to_tf32(ssp_f(acc[mt][nt][3] + boo[nt]));
            }
        }
        __syncthreads();

        gemm32x32(pa, pbd, acc);

        // final epilogue: v = D + bd; y = x + v
#pragma unroll
        for (int mt = 0; mt < 2; ++mt)
#pragma unroll
            for (int half = 0; half < 2; ++half) {
                int r = base + mr + mt * 16 + half * 8 + g;
                if (r < na) {
#pragma unroll
                    for (int nt = 0; nt < 4; ++nt) {
                        int col = nc + nt * 8 + 2 * c;
                        float vx = acc[mt][nt][half * 2]     + bde[nt];
                        float vy = acc[mt][nt][half * 2 + 1] + bdo[nt];
                        float2 xv = *(const float2*)(&x[(size_t)r * C + col]);
                        *(float2*)(&out_v[(size_t)r * C + col]) = make_float2(vx, vy);
                        *(float2*)(&out_y[(size_t)r * C + col]) = make_float2(xv.x + vx, xv.y + vy);
                    }
                }
            }
        __syncthreads();   // sA reads done before next tile overwrites
    }
}

// ---------------- transpose 5 weights W[k][n] -> Wt[n][k] ----------------
extern "C" __global__ void k_tr5(const float* __restrict__ s0, const float* __restrict__ s1,
                                 const float* __restrict__ s2, const float* __restrict__ s3,
                                 const float* __restrict__ s4) {
    __shared__ float t[32][33];
    const float* s; float* d;
    switch (blockIdx.z) {
        case 0: s = s0; d = g_W1t; break;
        case 1: s = s1; d = g_W2t; break;
        case 2: s = s2; d = g_Wit; break;
        case 3: s = s3; d = g_Wot; break;
        default: s = s4; d = g_Wdt; break;
    }
    int bx = blockIdx.x, by = blockIdx.y;
    int xx = threadIdx.x, yy = threadIdx.y;
#pragma unroll
    for (int i = 0; i < 32; i += 8) t[yy + i][xx] = s[(by * 32 + yy + i) * C + bx * 32 + xx];
    __syncthreads();
#pragma unroll
    for (int i = 0; i < 32; i += 8) d[(bx * 32 + yy + i) * C + by * 32 + xx] = t[xx][yy + i];
}

// ============================ launch ============================
extern "C" void kernel_launch(void* const* d_in, const int* in_sizes, int n_in,
                              void* d_out, int out_size) {
    const float* x    = (const float*)d_in[0];
    const float* dijk = (const float*)d_in[1];
    const int*   idxj = (const int*)d_in[2];
    const int*   segi = (const int*)d_in[3];
    const int*   segj = (const int*)d_in[4];
    const float* W1   = (const float*)d_in[5];
    const float* b1   = (const float*)d_in[6];
    const float* W2   = (const float*)d_in[7];
    const float* b2   = (const float*)d_in[8];
    const float* Wi   = (const float*)d_in[9];
    const float* Wo   = (const float*)d_in[10];
    const float* bo   = (const float*)d_in[11];
    const float* Wd   = (const float*)d_in[12];
    const float* bd   = (const float*)d_in[13];

    int na = in_sizes[0] / C;
    int ne = in_sizes[2];
    int ntt = (ne + TME - 1) / TME;
    int nta = (na + 127) / 128;
    int g_atoms = nta < 148 ? nta : 148;

    float* out_y = (float*)d_out;
    float* out_v = out_y + (size_t)na * C;

    const int SM_XF   = 2 * 128 * LDK * 4;                          // 139264
    const int SM_OUT  = 3 * 128 * LDK * 4;                          // 208896
    const int SM_EDGE = (NG * TME + 2 * 128) * LDK * 4 + 2048;      // 210944

    cudaFuncSetAttribute(k_xf_mma,    cudaFuncAttributeMaxDynamicSharedMemorySize, SM_XF);
    cudaFuncSetAttribute(k_out_mma,   cudaFuncAttributeMaxDynamicSharedMemorySize, SM_OUT);
    cudaFuncSetAttribute(k_edges_mma, cudaFuncAttributeMaxDynamicSharedMemorySize, SM_EDGE);

    k_tr5<<<dim3(4, 4, 5), dim3(32, 8)>>>(W1, W2, Wi, Wo, Wd);
    k_xf_mma<<<g_atoms, 512, SM_XF>>>(x, na, nta);
    k_edges_mma<<<148, 512, SM_EDGE>>>(dijk, idxj, segi, segj, b1, b2, ne, ntt);
    k_out_mma<<<g_atoms, 512, SM_OUT>>>(x, bo, bd, out_y, out_v, na, nta);
}

// round 15
// speedup vs baseline: 1.1997x; 1.0353x over previous
#include <cuda_runtime.h>
#include <cstdint>

#define C   128
#define LDK 136   // smem row stride (floats): 8-bank stride => conflict-free LDS.64
#define TME 32    // edge tile rows per group
#define NG  4     // independent warp-groups per CTA (edge)

extern __shared__ char dynsmem[];

// ---------------- scratch (device globals; allocation-free rule) ----------------
static __device__ __align__(16) float g_xf[20480 * C];
static __device__ __align__(16) float g_agg[20480 * C];
static __device__ __align__(16) float g_W1t[C * C];
static __device__ __align__(16) float g_W2t[C * C];
static __device__ __align__(16) float g_Wit[C * C];
static __device__ __align__(16) float g_Wot[C * C];
static __device__ __align__(16) float g_Wdt[C * C];

__device__ __forceinline__ float ssp_f(float x) {
    float t = __expf(-fabsf(x));
    return fmaxf(x, 0.0f) + __logf(1.0f + t) - 0.693147180559945f;
}

__device__ __forceinline__ float to_tf32(float x) {
    uint32_t u;
    asm("cvt.rna.tf32.f32 %0, %1;" : "=r"(u) : "f"(x));
    return __uint_as_float(u);
}

__device__ __forceinline__ void mma_tf32(float* d, const uint32_t* a, const uint32_t* b) {
    asm volatile(
        "mma.sync.aligned.m16n8k8.row.col.f32.tf32.tf32.f32 "
        "{%0,%1,%2,%3}, {%4,%5,%6,%7}, {%8,%9}, {%0,%1,%2,%3};"
        : "+f"(d[0]), "+f"(d[1]), "+f"(d[2]), "+f"(d[3])
        : "r"(a[0]), "r"(a[1]), "r"(a[2]), "r"(a[3]), "r"(b[0]), "r"(b[1]));
}

// Octet k-interleave: logical k j8 -> phys ((j8&3)<<1)|(j8>>2); pair {2c,2c+1} is one LDS.64.

__device__ __forceinline__ void load_w_tile(float* dst, const float* __restrict__ src,
                                            int tid, int nthr) {
    for (int idx = tid; idx < 128 * 32; idx += nthr) {
        int row = idx >> 5, c4 = idx & 31;
        float4 v = ((const float4*)src)[idx];
        float* d = dst + row * LDK + (c4 >> 1) * 8 + (c4 & 1);
        d[0] = to_tf32(v.x); d[2] = to_tf32(v.y); d[4] = to_tf32(v.z); d[6] = to_tf32(v.w);
    }
}

// one warp's 32x32 output tile over k=128
__device__ __forceinline__ void gemm32x32(const float* pa, const float* pb, float acc[2][4][4]) {
#pragma unroll
    for (int mt = 0; mt < 2; ++mt)
#pragma unroll
        for (int nt = 0; nt < 4; ++nt)
#pragma unroll
            for (int q = 0; q < 4; ++q) acc[mt][nt][q] = 0.f;
#pragma unroll
    for (int kk = 0; kk < 16; ++kk) {
        const int kb = kk * 8;
        uint32_t af[2][4], bf[4][2];
#pragma unroll
        for (int mt = 0; mt < 2; ++mt) {
            float2 xv = *(const float2*)(pa + mt * 16 * LDK + kb);
            float2 yv = *(const float2*)(pa + (mt * 16 + 8) * LDK + kb);
            af[mt][0] = __float_as_uint(xv.x); af[mt][2] = __float_as_uint(xv.y);
            af[mt][1] = __float_as_uint(yv.x); af[mt][3] = __float_as_uint(yv.y);
        }
#pragma unroll
        for (int nt = 0; nt < 4; ++nt) {
            float2 zv = *(const float2*)(pb + nt * 8 * LDK + kb);
            bf[nt][0] = __float_as_uint(zv.x); bf[nt][1] = __float_as_uint(zv.y);
        }
#pragma unroll
        for (int mt = 0; mt < 2; ++mt)
#pragma unroll
            for (int nt = 0; nt < 4; ++nt)
                mma_tf32(acc[mt][nt], af[mt], bf[nt]);
    }
}

#define BARG() asm volatile("bar.sync %0, 128;" :: "r"(grp + 1) : "memory")

// =====================================================================
// Edge kernel: 4 independent 4-warp groups; register-prefetched A tiles;
// biases in registers.  agg += scatter(ssp(ssp(dijk@W1+b1)@W2+b2)*xf[idx_j])
// =====================================================================
extern "C" __global__ void __launch_bounds__(512, 1)
k_edges_mma(const float* __restrict__ dijk,
            const int* __restrict__ idx_j,
            const int* __restrict__ seg_i,
            const int* __restrict__ seg_j,
            const float* __restrict__ b1, const float* __restrict__ b2,
            int ne, int ntt) {
    float* sA0 = (float*)dynsmem;                 // NG x (32 x LDK)
    float* sB1 = sA0 + NG * TME * LDK;            // W1t 128 x LDK
    float* sB2 = sB1 + 128 * LDK;                 // W2t 128 x LDK
    int*   sg  = (int*)(sB2 + 128 * LDK);         // [NG][64] gather

    const int tid = threadIdx.x;
    const int grp = tid >> 7, gt = tid & 127;     // 4 groups of 128 threads
    const int wid = gt >> 5, lane = tid & 31;
    const int g = lane >> 2, c = lane & 3;
    const int nc = wid * 32;                      // warp col-block (mr = 0 for all)
    const int pe = ((c & 1) << 2) + (c >> 1);     // phys pos of logical col 2c within octet
    const int po = pe + 2;

    float* sA  = sA0 + grp * TME * LDK;
    int* s_aj = sg + grp * 64;
    int* s_ti = s_aj + TME;

    // per-thread bias registers for the 8 columns this thread owns (per n-tile)
    float be1[4], bo1[4], be2[4], bo2[4];
#pragma unroll
    for (int nt = 0; nt < 4; ++nt) {
        int col = nc + nt * 8 + 2 * c;
        be1[nt] = b1[col]; bo1[nt] = b1[col + 1];
        be2[nt] = b2[col]; bo2[nt] = b2[col + 1];
    }

    load_w_tile(sB1, g_W1t, tid, 512);
    load_w_tile(sB2, g_W2t, tid, 512);
    __syncthreads();

    const float* pa  = sA  + g * LDK + 2 * c;
    const float* pb1 = sB1 + (nc + g) * LDK + 2 * c;
    const float* pb2 = sB2 + (nc + g) * LDK + 2 * c;

    const int tstride = gridDim.x * NG;
    int t = blockIdx.x * NG + grp;

    // per-thread A-row mapping for the 8 prefetch quads
    const int prow = gt >> 5;        // base row (advances by 4 per quad)
    const int pc4  = gt & 31;

    // ---- prologue prefetch for first tile ----
    float4 pf[8];
    int pf_aj = 0, pf_ti = -1;
    {
        int base = t * TME;
#pragma unroll
        for (int i = 0; i < 8; ++i) {
            int gr = base + prow + i * 4;
            pf[i] = (t < ntt && gr < ne) ? ((const float4*)dijk)[gr * 32 + pc4]
                                         : make_float4(0.f, 0.f, 0.f, 0.f);
        }
        if (gt < TME) {
            int e = base + gt;
            if (t < ntt && e < ne) { int p = seg_j[e]; pf_aj = idx_j[p]; pf_ti = seg_i[p]; }
        }
    }

    for (; t < ntt; ) {
        // ---- commit prefetched tile to smem ----
#pragma unroll
        for (int i = 0; i < 8; ++i) {
            int row = prow + i * 4;
            float* d = sA + row * LDK + (pc4 >> 1) * 8 + (pc4 & 1);
            d[0] = to_tf32(pf[i].x); d[2] = to_tf32(pf[i].y);
            d[4] = to_tf32(pf[i].z); d[6] = to_tf32(pf[i].w);
        }
        if (gt < TME) { s_aj[gt] = pf_aj; s_ti[gt] = pf_ti; }
        BARG();

        // ---- issue prefetch for next tile (drains behind the GEMMs) ----
        const int tn = t + tstride;
        {
            int base = tn * TME;
#pragma unroll
            for (int i = 0; i < 8; ++i) {
                int gr = base + prow + i * 4;
                pf[i] = (tn < ntt && gr < ne) ? ((const float4*)dijk)[gr * 32 + pc4]
                                              : make_float4(0.f, 0.f, 0.f, 0.f);
            }
            pf_aj = 0; pf_ti = -1;
            if (gt < TME) {
                int e = base + gt;
                if (tn < ntt && e < ne) { int p = seg_j[e]; pf_aj = idx_j[p]; pf_ti = seg_i[p]; }
            }
        }

        float acc[2][4][4];
        gemm32x32(pa, pb1, acc);
        BARG();

        // epi1: H = tf32(ssp(D + b1)) -> sA
#pragma unroll
        for (int mt = 0; mt < 2; ++mt) {
            int row = mt * 16 + g;
#pragma unroll
            for (int nt = 0; nt < 4; ++nt) {
                float* d0 = sA + row * LDK + nc + nt * 8;
                float* d1 = d0 + 8 * LDK;
                d0[pe] = to_tf32(ssp_f(acc[mt][nt][0] + be1[nt]));
                d0[po] = to_tf32(ssp_f(acc[mt][nt][1] + bo1[nt]));
                d1[pe] = to_tf32(ssp_f(acc[mt][nt][2] + be1[nt]));
                d1[po] = to_tf32(ssp_f(acc[mt][nt][3] + bo1[nt]));
            }
        }
        BARG();

        gemm32x32(pa, pb2, acc);
        BARG();

        // epi2a: W = ssp(D + b2) -> sA (fp32)
#pragma unroll
        for (int mt = 0; mt < 2; ++mt) {
            int row = mt * 16 + g;
#pragma unroll
            for (int nt = 0; nt < 4; ++nt) {
                float* d0 = sA + row * LDK + nc + nt * 8;
                float* d1 = d0 + 8 * LDK;
                d0[pe] = ssp_f(acc[mt][nt][0] + be2[nt]);
                d0[po] = ssp_f(acc[mt][nt][1] + bo2[nt]);
                d1[pe] = ssp_f(acc[mt][nt][2] + be2[nt]);
                d1[po] = ssp_f(acc[mt][nt][3] + bo2[nt]);
            }
        }
        BARG();

        // epi2b: msg = W * xf[aj]; run-length reduce over sorted targets
        {
            const int col = gt;
            const int pc = (col & ~7) + ((col & 3) << 1) + ((col >> 2) & 1);
            float acc1 = 0.f;
            int cur = -1;
#pragma unroll
            for (int row = 0; row < TME; ++row) {
                int tgt = s_ti[row];
                float wv = sA[row * LDK + pc];
                float xv = __ldg(&g_xf[(size_t)s_aj[row] * C + col]);
                if (tgt != cur) {
                    if (cur >= 0) atomicAdd(&g_agg[(size_t)cur * C + col], acc1);
                    acc1 = 0.f; cur = tgt;
                }
                acc1 = fmaf(wv, xv, acc1);
            }
            if (cur >= 0) atomicAdd(&g_agg[(size_t)cur * C + col], acc1);
        }
        BARG();
        t = tn;
    }
}

// A-tile commit helper: 8 prefetched float4 quads -> swizzled smem (512 threads)
__device__ __forceinline__ void commit_a(float* sA, const float4* pf, int tid) {
#pragma unroll
    for (int i = 0; i < 8; ++i) {
        int idx = tid + i * 512;
        int row = idx >> 5, c4 = idx & 31;
        float* d = sA + row * LDK + (c4 >> 1) * 8 + (c4 & 1);
        d[0] = to_tf32(pf[i].x); d[2] = to_tf32(pf[i].y);
        d[4] = to_tf32(pf[i].z); d[6] = to_tf32(pf[i].w);
    }
}

__device__ __forceinline__ void fetch_a(float4* pf, const float* __restrict__ src,
                                        int base, int nrow_total, int ok, int tid) {
#pragma unroll
    for (int i = 0; i < 8; ++i) {
        int idx = tid + i * 512;
        int gr = base + (idx >> 5);
        pf[i] = (ok && gr < nrow_total) ? ((const float4*)src)[gr * 32 + (idx & 31)]
                                        : make_float4(0.f, 0.f, 0.f, 0.f);
    }
}

// =====================================================================
// k_xf (persistent, A-prefetched): xf = x @ Wi; zeroes g_agg per tile
// =====================================================================
extern "C" __global__ void __launch_bounds__(512, 1)
k_xf_mma(const float* __restrict__ x, int na, int ntiles) {
    float* sA = (float*)dynsmem;        // 128 x LDK
    float* sB = sA + 128 * LDK;         // Wit
    const int tid = threadIdx.x, wid = tid >> 5, lane = tid & 31;
    const int g = lane >> 2, c = lane & 3;
    const int mr = (wid & 3) * 32, nc = (wid >> 2) * 32;

    int t = blockIdx.x;
    float4 pf[8];
    fetch_a(pf, x, t * 128, na, t < ntiles, tid);   // A LDGs issue before weight load

    load_w_tile(sB, g_Wit, tid, 512);

    const float* pa = sA + (mr + g) * LDK + 2 * c;
    const float* pb = sB + (nc + g) * LDK + 2 * c;

    for (; t < ntiles; ) {
        const int base = t * 128;
        commit_a(sA, pf, tid);

        // zero agg for this tile (overlaps with barrier/GEMM)
        for (int idx = tid; idx < 128 * 32; idx += 512) {
            int row = idx >> 5, c4 = idx & 31;
            int gr = base + row;
            if (gr < na) ((float4*)(g_agg + (size_t)gr * C))[c4] = make_float4(0.f, 0.f, 0.f, 0.f);
        }
        const int tn = t + gridDim.x;
        fetch_a(pf, x, tn * 128, na, tn < ntiles, tid);
        __syncthreads();

        float acc[2][4][4];
        gemm32x32(pa, pb, acc);

#pragma unroll
        for (int mt = 0; mt < 2; ++mt)
#pragma unroll
            for (int half = 0; half < 2; ++half) {
                int r = base + mr + mt * 16 + half * 8 + g;
                if (r < na) {
#pragma unroll
                    for (int nt = 0; nt < 4; ++nt) {
                        int col = nc + nt * 8 + 2 * c;
                        float2 v = make_float2(acc[mt][nt][half * 2], acc[mt][nt][half * 2 + 1]);
                        *(float2*)(&g_xf[(size_t)r * C + col]) = v;
                    }
                }
            }
        __syncthreads();   // sA reads done before next tile overwrites
        t = tn;
    }
}

// =====================================================================
// k_out (persistent, A-prefetched): h = ssp(agg@Wo+bo); v = h@Wd+bd; y = x+v
// =====================================================================
extern "C" __global__ void __launch_bounds__(512, 1)
k_out_mma(const float* __restrict__ x,
          const float* __restrict__ bo, const float* __restrict__ bd,
          float* __restrict__ out_y, float* __restrict__ out_v, int na, int ntiles) {
    float* sA  = (float*)dynsmem;       // 128 x LDK
    float* sBo = sA + 128 * LDK;        // Wot
    float* sBd = sBo + 128 * LDK;       // Wdt
    const int tid = threadIdx.x, wid = tid >> 5, lane = tid & 31;
    const int g = lane >> 2, c = lane & 3;
    const int mr = (wid & 3) * 32, nc = (wid >> 2) * 32;
    const int pe = ((c & 1) << 2) + (c >> 1);
    const int po = pe + 2;

    float boe[4], boo[4], bde[4], bdo[4];
#pragma unroll
    for (int nt = 0; nt < 4; ++nt) {
        int col = nc + nt * 8 + 2 * c;
        boe[nt] = bo[col]; boo[nt] = bo[col + 1];
        bde[nt] = bd[col]; bdo[nt] = bd[col + 1];
    }

    int t = blockIdx.x;
    float4 pf[8];
    fetch_a(pf, g_agg, t * 128, na, t < ntiles, tid);   // A LDGs before weight loads

    load_w_tile(sBo, g_Wot, tid, 512);
    load_w_tile(sBd, g_Wdt, tid, 512);

    const float* pa  = sA + (mr + g) * LDK + 2 * c;
    const float* pbo = sBo + (nc + g) * LDK + 2 * c;
    const float* pbd = sBd + (nc + g) * LDK + 2 * c;

    for (; t < ntiles; ) {
        const int base = t * 128;
        commit_a(sA, pf, tid);
        const int tn = t + gridDim.x;
        fetch_a(pf, g_agg, tn * 128, na, tn < ntiles, tid);
        __syncthreads();

        float acc[2][4][4];
        gemm32x32(pa, pbo, acc);
        __syncthreads();   // all warps done reading sA

        // epi1: H = tf32(ssp(D + bo)) -> sA
#pragma unroll
        for (int mt = 0; mt < 2; ++mt) {
            int row = mr + mt * 16 + g;
#pragma unroll
            for (int nt = 0; nt < 4; ++nt) {
                float* d0 = sA + row * LDK + nc + nt * 8;
                float* d1 = d0 + 8 * LDK;
                d0[pe] = to_tf32(ssp_f(acc[mt][nt][0] + boe[nt]));
                d0[po] = to_tf32(ssp_f(acc[mt][nt][1] + boo[nt]));
                d1[pe] = to_tf32(ssp_f(acc[mt][nt][2] + boe[nt]));
                d1[po] = to_tf32(ssp_f(acc[mt][nt][3] + boo[nt]));
            }
        }
        __syncthreads();

        gemm32x32(pa, pbd, acc);

        // final epilogue: v = D + bd; y = x + v
#pragma unroll
        for (int mt = 0; mt < 2; ++mt)
#pragma unroll
            for (int half = 0; half < 2; ++half) {
                int r = base + mr + mt * 16 + half * 8 + g;
                if (r < na) {
#pragma unroll
                    for (int nt = 0; nt < 4; ++nt) {
                        int col = nc + nt * 8 + 2 * c;
                        float vx = acc[mt][nt][half * 2]     + bde[nt];
                        float vy = acc[mt][nt][half * 2 + 1] + bdo[nt];
                        float2 xv = *(const float2*)(&x[(size_t)r * C + col]);
                        *(float2*)(&out_v[(size_t)r * C + col]) = make_float2(vx, vy);
                        *(float2*)(&out_y[(size_t)r * C + col]) = make_float2(xv.x + vx, xv.y + vy);
                    }
                }
            }
        __syncthreads();   // sA reads done before next tile overwrites
        t = tn;
    }
}

// ---------------- transpose 5 weights W[k][n] -> Wt[n][k] ----------------
extern "C" __global__ void k_tr5(const float* __restrict__ s0, const float* __restrict__ s1,
                                 const float* __restrict__ s2, const float* __restrict__ s3,
                                 const float* __restrict__ s4) {
    __shared__ float t[32][33];
    const float* s; float* d;
    switch (blockIdx.z) {
        case 0: s = s0; d = g_W1t; break;
        case 1: s = s1; d = g_W2t; break;
        case 2: s = s2; d = g_Wit; break;
        case 3: s = s3; d = g_Wot; break;
        default: s = s4; d = g_Wdt; break;
    }
    int bx = blockIdx.x, by = blockIdx.y;
    int xx = threadIdx.x, yy = threadIdx.y;
#pragma unroll
    for (int i = 0; i < 32; i += 8) t[yy + i][xx] = s[(by * 32 + yy + i) * C + bx * 32 + xx];
    __syncthreads();
#pragma unroll
    for (int i = 0; i < 32; i += 8) d[(bx * 32 + yy + i) * C + by * 32 + xx] = t[xx][yy + i];
}

// ============================ launch ============================
extern "C" void kernel_launch(void* const* d_in, const int* in_sizes, int n_in,
                              void* d_out, int out_size) {
    const float* x    = (const float*)d_in[0];
    const float* dijk = (const float*)d_in[1];
    const int*   idxj = (const int*)d_in[2];
    const int*   segi = (const int*)d_in[3];
    const int*   segj = (const int*)d_in[4];
    const float* W1   = (const float*)d_in[5];
    const float* b1   = (const float*)d_in[6];
    const float* W2   = (const float*)d_in[7];
    const float* b2   = (const float*)d_in[8];
    const float* Wi   = (const float*)d_in[9];
    const float* Wo   = (const float*)d_in[10];
    const float* bo   = (const float*)d_in[11];
    const float* Wd   = (const float*)d_in[12];
    const float* bd   = (const float*)d_in[13];

    int na = in_sizes[0] / C;
    int ne = in_sizes[2];
    int ntt = (ne + TME - 1) / TME;
    int nta = (na + 127) / 128;
    int g_atoms = nta < 148 ? nta : 148;

    float* out_y = (float*)d_out;
    float* out_v = out_y + (size_t)na * C;

    const int SM_XF   = 2 * 128 * LDK * 4;                          // 139264
    const int SM_OUT  = 3 * 128 * LDK * 4;                          // 208896
    const int SM_EDGE = (NG * TME + 2 * 128) * LDK * 4 + 1024;      // 209920

    cudaFuncSetAttribute(k_xf_mma,    cudaFuncAttributeMaxDynamicSharedMemorySize, SM_XF);
    cudaFuncSetAttribute(k_out_mma,   cudaFuncAttributeMaxDynamicSharedMemorySize, SM_OUT);
    cudaFuncSetAttribute(k_edges_mma, cudaFuncAttributeMaxDynamicSharedMemorySize, SM_EDGE);

    k_tr5<<<dim3(4, 4, 5), dim3(32, 8)>>>(W1, W2, Wi, Wo, Wd);
    k_xf_mma<<<g_atoms, 512, SM_XF>>>(x, na, nta);
    k_edges_mma<<<148, 512, SM_EDGE>>>(dijk, idxj, segi, segj, b1, b2, ne, ntt);
    k_out_mma<<<g_atoms, 512, SM_OUT>>>(x, bo, bd, out_y, out_v, na, nta);
}